// round 6
// baseline (speedup 1.0000x reference)
#include <cuda_runtime.h>
#include <cuda_bf16.h>

// Problem: input/label [32, 3, 512, 512] f32 in [0,256).
// Per-channel 256-bin histograms (bin = floor(clip(v,0,255))), Bhattacharyya
// distance per channel, summed -> scalar f32.
//
// Numerics: per-channel t = 1 - s/denom ~ 7.6e-6 is a catastrophic
// cancellation; rel_err < 1e-3 requires |delta s| < ~0.4, i.e. bit-exact
// replication of the reference's float32 summation order for
// s = sum(sqrt(h1*h2)). denom is provably exact (2^23). This round
// replicates the legacy XLA:GPU row-reduction emitter:
//   32 threads, vector_size=2, strided loads e[64*j + 2*t + v] (j=0..3),
//   per-vector-lane accumulators a0/a1, INDEPENDENT shfl-down trees
//   (16,8,4,2,1) for a0 and a1, then s = tree(a0) + tree(a1) on lane 0.
// (R4 tried tree(a0+a1): rel_err 3.9e-3, delta-s ~1.5 counts.)

#define NBINS 256
#define NCH 3
#define NHIST (2 * NCH * NBINS)   // input hists [0..767], label hists [768..1535]

__device__ unsigned int g_hist[NHIST];

__global__ void his_zero_kernel() {
    int i = blockIdx.x * blockDim.x + threadIdx.x;
    if (i < NHIST) g_hist[i] = 0u;
}

__global__ void __launch_bounds__(256) his_hist_kernel(
    const float4* __restrict__ a,   // input
    const float4* __restrict__ b,   // label
    int n4)
{
    __shared__ unsigned int sh[NHIST];
    for (int i = threadIdx.x; i < NHIST; i += blockDim.x) sh[i] = 0u;
    __syncthreads();

    const int stride = gridDim.x * blockDim.x;
    for (int i = blockIdx.x * blockDim.x + threadIdx.x; i < n4; i += stride) {
        // channel of this float4: each (b,c) plane is 65536 float4
        int plane = i >> 16;
        int c = plane - (plane / 3) * 3;  // plane % 3
        unsigned int baseA = (unsigned int)(c * NBINS);
        unsigned int baseB = baseA + (unsigned int)(NCH * NBINS);

        float4 va = a[i];
        float4 vb = b[i];

        int ax = (int)va.x; ax = ax < 0 ? 0 : (ax > 255 ? 255 : ax);
        int ay = (int)va.y; ay = ay < 0 ? 0 : (ay > 255 ? 255 : ay);
        int az = (int)va.z; az = az < 0 ? 0 : (az > 255 ? 255 : az);
        int aw = (int)va.w; aw = aw < 0 ? 0 : (aw > 255 ? 255 : aw);
        int bx = (int)vb.x; bx = bx < 0 ? 0 : (bx > 255 ? 255 : bx);
        int by = (int)vb.y; by = by < 0 ? 0 : (by > 255 ? 255 : by);
        int bz = (int)vb.z; bz = bz < 0 ? 0 : (bz > 255 ? 255 : bz);
        int bw = (int)vb.w; bw = bw < 0 ? 0 : (bw > 255 ? 255 : bw);

        atomicAdd(&sh[baseA + (unsigned int)ax], 1u);
        atomicAdd(&sh[baseA + (unsigned int)ay], 1u);
        atomicAdd(&sh[baseA + (unsigned int)az], 1u);
        atomicAdd(&sh[baseA + (unsigned int)aw], 1u);
        atomicAdd(&sh[baseB + (unsigned int)bx], 1u);
        atomicAdd(&sh[baseB + (unsigned int)by], 1u);
        atomicAdd(&sh[baseB + (unsigned int)bz], 1u);
        atomicAdd(&sh[baseB + (unsigned int)bw], 1u);
    }
    __syncthreads();

    for (int i = threadIdx.x; i < NHIST; i += blockDim.x) {
        unsigned int v = sh[i];
        if (v) atomicAdd(&g_hist[i], v);
    }
}

// One warp. Legacy XLA:GPU row-reduce order: independent shuffle trees per
// vector lane, combined after the trees.
__global__ void his_final_kernel(float* __restrict__ out) {
    const int lane = threadIdx.x;
    if (blockIdx.x != 0 || lane >= 32) return;

    float total = 0.0f;
    #pragma unroll 1
    for (int c = 0; c < NCH; c++) {
        const unsigned int* h1 = &g_hist[c * NBINS];
        const unsigned int* h2 = &g_hist[NCH * NBINS + c * NBINS];

        // strided vec2 accumulation: a_v += e[64*j + 2*lane + v], j ascending
        float a0 = 0.0f, a1 = 0.0f;
        unsigned int isum1 = 0u, isum2 = 0u;   // exact integer totals
        #pragma unroll
        for (int j = 0; j < 4; j++) {
            int base = j * 64 + lane * 2;
            float t0 = __fsqrt_rn(__fmul_rn((float)h1[base],     (float)h2[base]));
            float t1 = __fsqrt_rn(__fmul_rn((float)h1[base + 1], (float)h2[base + 1]));
            a0 = __fadd_rn(a0, t0);
            a1 = __fadd_rn(a1, t1);
            isum1 += h1[base] + h1[base + 1];
            isum2 += h2[base] + h2[base + 1];
        }

        // independent full shfl-down trees for each vector-lane accumulator
        #pragma unroll
        for (int d = 16; d >= 1; d >>= 1) {
            a0 = __fadd_rn(a0, __shfl_down_sync(0xffffffffu, a0, d));
            a1 = __fadd_rn(a1, __shfl_down_sync(0xffffffffu, a1, d));
        }
        // combine vector partials AFTER the trees (legacy emitter order)
        float s = __fadd_rn(__shfl_sync(0xffffffffu, a0, 0),
                            __shfl_sync(0xffffffffu, a1, 0));

        // integer totals: order-independent exact
        #pragma unroll
        for (int d = 16; d >= 1; d >>= 1) {
            isum1 += __shfl_down_sync(0xffffffffu, isum1, d);
            isum2 += __shfl_down_sync(0xffffffffu, isum2, d);
        }
        unsigned int n1 = __shfl_sync(0xffffffffu, isum1, 0);
        unsigned int n2 = __shfl_sync(0xffffffffu, isum2, 0);

        // denom = sqrt(mean1*mean2)*256 (all ops exact for these values)
        float m1 = __fdiv_rn((float)n1, 256.0f);
        float m2 = __fdiv_rn((float)n2, 256.0f);
        float denom = __fmul_rn(__fsqrt_rn(__fmul_rn(m1, m2)), 256.0f);

        float r = __fdiv_rn(s, denom);
        float t = __fadd_rn(1.0f, -r);   // Sterbenz-exact for r near 1
        if (t < 0.0f) t = 0.0f;
        total = __fadd_rn(total, __fsqrt_rn(t));
    }
    if (lane == 0) out[0] = total;
}

extern "C" void kernel_launch(void* const* d_in, const int* in_sizes, int n_in,
                              void* d_out, int out_size) {
    const float4* a = (const float4*)d_in[0];
    const float4* b = (const float4*)d_in[1];
    float* out = (float*)d_out;

    int n4 = in_sizes[0] >> 2;

    his_zero_kernel<<<(NHIST + 255) / 256, 256>>>();
    his_hist_kernel<<<1184, 256>>>(a, b, n4);   // 8 blocks/SM * 148 SMs
    his_final_kernel<<<1, 32>>>(out);
}

// round 8
// speedup vs baseline: 1.0404x; 1.0404x over previous
#include <cuda_runtime.h>
#include <cuda_bf16.h>

// his_19834158972940: input/label [32,3,512,512] f32 in [0,256).
// Per-channel 256-bin histograms + Bhattacharyya distance, summed -> f32.
//
// Numerics (verified R5, rel_err 0.0): t = 1 - s/denom ~ 7.6e-6 is a
// catastrophic cancellation; passing requires BIT-EXACT replication of the
// reference's float32 reduction order for s = sum(sqrt(h1*h2)):
// legacy XLA:GPU row-reduce — 32 threads, vector_size=2, strided loads
// e[64j+2t+v], independent shfl-down trees (16,8,4,2,1) per vector lane,
// combined AFTER the trees. denom is exact (2^23). Preserved verbatim.
//
// Perf: single fused persistent kernel.
//  - 8-way smem sub-histograms keyed by lane&7, layout (region+bin)*8+copy:
//    bank = (bin*8+copy)%32 -> conflicts need same copy AND same bin%4
//    among 4 lanes -> conflict degree ~2 vs ~4 unreplicated.
//  - no zero kernel: __device__ globals start zeroed; the last block
//    re-zeroes state at the end, so every graph replay sees zeros.
//  - no finalize kernel: threadfence + arrival counter, last block reduces.

#define NBINS 256
#define NCH 3
#define NHIST (2 * NCH * NBINS)   // input hists [0..767], label hists [768..1535]
#define REP 8
#define THREADS 512
#define BLOCKS 592                // 4 blocks/SM * 148 SMs

__device__ unsigned int g_hist[NHIST];   // zero-initialized at module load
__device__ unsigned int g_count;         // arrival counter, reset each call

__global__ void __launch_bounds__(THREADS) his_fused_kernel(
    const float4* __restrict__ a,   // input
    const float4* __restrict__ b,   // label
    int n4,
    float* __restrict__ out)
{
    __shared__ unsigned int sh[NHIST * REP];   // 49152 B (static smem limit)
    const int tid = threadIdx.x;

    for (int i = tid; i < NHIST * REP; i += THREADS) sh[i] = 0u;
    __syncthreads();

    const unsigned int c8 = (unsigned int)(tid & 7);
    const int stride = gridDim.x * blockDim.x;
    for (int i = blockIdx.x * blockDim.x + tid; i < n4; i += stride) {
        // channel of this float4: each (b,c) plane is 65536 float4
        int plane = i >> 16;
        int c = plane - (plane / 3) * 3;  // plane % 3
        unsigned int baseA = (unsigned int)(c * NBINS) * REP + c8;
        unsigned int baseB = baseA + (unsigned int)(NCH * NBINS) * REP;

        float4 va = a[i];
        float4 vb = b[i];

        // bin = clip(v,0,255) then truncate (values >= 0)
        int ax = (int)va.x; ax = ax < 0 ? 0 : (ax > 255 ? 255 : ax);
        int ay = (int)va.y; ay = ay < 0 ? 0 : (ay > 255 ? 255 : ay);
        int az = (int)va.z; az = az < 0 ? 0 : (az > 255 ? 255 : az);
        int aw = (int)va.w; aw = aw < 0 ? 0 : (aw > 255 ? 255 : aw);
        int bx = (int)vb.x; bx = bx < 0 ? 0 : (bx > 255 ? 255 : bx);
        int by = (int)vb.y; by = by < 0 ? 0 : (by > 255 ? 255 : by);
        int bz = (int)vb.z; bz = bz < 0 ? 0 : (bz > 255 ? 255 : bz);
        int bw = (int)vb.w; bw = bw < 0 ? 0 : (bw > 255 ? 255 : bw);

        atomicAdd(&sh[baseA + (unsigned int)(ax << 3)], 1u);
        atomicAdd(&sh[baseA + (unsigned int)(ay << 3)], 1u);
        atomicAdd(&sh[baseA + (unsigned int)(az << 3)], 1u);
        atomicAdd(&sh[baseA + (unsigned int)(aw << 3)], 1u);
        atomicAdd(&sh[baseB + (unsigned int)(bx << 3)], 1u);
        atomicAdd(&sh[baseB + (unsigned int)(by << 3)], 1u);
        atomicAdd(&sh[baseB + (unsigned int)(bz << 3)], 1u);
        atomicAdd(&sh[baseB + (unsigned int)(bw << 3)], 1u);
    }
    __syncthreads();

    // Flush block-private histogram (sum of 8 copies) to global.
    for (int i = tid; i < NHIST; i += THREADS) {
        unsigned int v = 0;
        #pragma unroll
        for (int r = 0; r < REP; r++) v += sh[i * REP + r];
        if (v) atomicAdd(&g_hist[i], v);
    }

    // Last-block detection (threadFenceReduction pattern).
    __shared__ unsigned int s_last;
    __threadfence();
    if (tid == 0) {
        unsigned int prev = atomicAdd(&g_count, 1u);
        s_last = (prev == (unsigned int)gridDim.x - 1u) ? 1u : 0u;
    }
    __syncthreads();
    if (!s_last) return;
    __threadfence();

    // ---- Final Bhattacharyya reduce: warp 0, bit-exact R5 code path ----
    if (tid < 32) {
        const int lane = tid;
        float total = 0.0f;
        #pragma unroll 1
        for (int c = 0; c < NCH; c++) {
            const unsigned int* h1 = &g_hist[c * NBINS];
            const unsigned int* h2 = &g_hist[NCH * NBINS + c * NBINS];

            // strided vec2 accumulation: a_v += e[64*j + 2*lane + v]
            float a0 = 0.0f, a1 = 0.0f;
            unsigned int isum1 = 0u, isum2 = 0u;
            #pragma unroll
            for (int j = 0; j < 4; j++) {
                int base = j * 64 + lane * 2;
                unsigned int u10 = __ldcg(&h1[base]);
                unsigned int u11 = __ldcg(&h1[base + 1]);
                unsigned int u20 = __ldcg(&h2[base]);
                unsigned int u21 = __ldcg(&h2[base + 1]);
                float t0 = __fsqrt_rn(__fmul_rn((float)u10, (float)u20));
                float t1 = __fsqrt_rn(__fmul_rn((float)u11, (float)u21));
                a0 = __fadd_rn(a0, t0);
                a1 = __fadd_rn(a1, t1);
                isum1 += u10 + u11;
                isum2 += u20 + u21;
            }

            // independent full shfl-down trees per vector-lane accumulator
            #pragma unroll
            for (int d = 16; d >= 1; d >>= 1) {
                a0 = __fadd_rn(a0, __shfl_down_sync(0xffffffffu, a0, d));
                a1 = __fadd_rn(a1, __shfl_down_sync(0xffffffffu, a1, d));
            }
            float s = __fadd_rn(__shfl_sync(0xffffffffu, a0, 0),
                                __shfl_sync(0xffffffffu, a1, 0));

            #pragma unroll
            for (int d = 16; d >= 1; d >>= 1) {
                isum1 += __shfl_down_sync(0xffffffffu, isum1, d);
                isum2 += __shfl_down_sync(0xffffffffu, isum2, d);
            }
            unsigned int n1 = __shfl_sync(0xffffffffu, isum1, 0);
            unsigned int n2 = __shfl_sync(0xffffffffu, isum2, 0);

            float m1 = __fdiv_rn((float)n1, 256.0f);
            float m2 = __fdiv_rn((float)n2, 256.0f);
            float denom = __fmul_rn(__fsqrt_rn(__fmul_rn(m1, m2)), 256.0f);

            float r = __fdiv_rn(s, denom);
            float t = __fadd_rn(1.0f, -r);   // Sterbenz-exact for r near 1
            if (t < 0.0f) t = 0.0f;
            total = __fadd_rn(total, __fsqrt_rn(t));
        }
        if (lane == 0) out[0] = total;
    }
    __syncthreads();

    // Restore global state to zeros for the next (graph-replayed) call.
    for (int i = tid; i < NHIST; i += THREADS) g_hist[i] = 0u;
    if (tid == 0) g_count = 0u;
}

extern "C" void kernel_launch(void* const* d_in, const int* in_sizes, int n_in,
                              void* d_out, int out_size) {
    const float4* a = (const float4*)d_in[0];
    const float4* b = (const float4*)d_in[1];
    float* out = (float*)d_out;

    int n4 = in_sizes[0] >> 2;   // 6291456 float4 per tensor

    his_fused_kernel<<<BLOCKS, THREADS>>>(a, b, n4, out);
}

// round 9
// speedup vs baseline: 1.1527x; 1.1080x over previous
#include <cuda_runtime.h>
#include <cuda_bf16.h>

// his_19834158972940: input/label [32,3,512,512] f32 in [0,256).
// Per-channel 256-bin histograms + Bhattacharyya distance, summed -> f32.
//
// Numerics (verified R5/R7, rel_err 0.0): t = 1 - s/denom ~ 7.6e-6 is a
// catastrophic cancellation; passing requires BIT-EXACT replication of the
// reference's float32 reduction order for s = sum(sqrt(h1*h2)):
// legacy XLA:GPU row-reduce — 32 threads, vector_size=2, strided loads
// e[64j+2t+v], independent shfl-down trees (16,8,4,2,1) per vector lane,
// combined AFTER the trees. denom exact (2^23). Preserved verbatim.
//
// Perf (R8): R7 ncu showed DRAM 53% / L1 49% / issue 29% — latency-bound on
// the smem-atomic chain (MIO backpressure + conflict replays), not any
// throughput ceiling. Changes:
//  - REP 16 (dynamic smem 96KB, 1024-thr blocks, 2 blocks/SM = full 2048
//    thr/SM). bank=(bin*16+copy)%32: cross-copy conflicts impossible,
//    within-copy only 2 lanes, need equal bin parity -> degree ~1.25.
//  - manual 2x unroll: 4 LDG.128 batched up front, then 16 atomics.
//  - still one fused kernel: last block reduces (bit-exact path) and
//    re-zeroes globals for graph replay.

#define NBINS 256
#define NCH 3
#define NHIST (2 * NCH * NBINS)   // input hists [0..767], label hists [768..1535]
#define REP 16
#define THREADS 1024
#define BLOCKS 296                // 2 blocks/SM * 148 SMs
#define SMEM_BYTES (NHIST * REP * 4)   // 98304

__device__ unsigned int g_hist[NHIST];   // zero-initialized at module load
__device__ unsigned int g_count;         // arrival counter, reset each call

__global__ void __launch_bounds__(THREADS) his_fused_kernel(
    const float4* __restrict__ a,   // input
    const float4* __restrict__ b,   // label
    int n4,
    float* __restrict__ out)
{
    extern __shared__ unsigned int sh[];   // NHIST * REP words
    const int tid = threadIdx.x;

    for (int i = tid; i < NHIST * REP; i += THREADS) sh[i] = 0u;
    __syncthreads();

    const unsigned int copy = (unsigned int)(tid & (REP - 1));
    const int stride = gridDim.x * blockDim.x;

    int i = blockIdx.x * blockDim.x + tid;
    for (; i + stride < n4; i += 2 * stride) {
        int i2 = i + stride;
        // batch all 4 loads first (MLP)
        float4 va0 = a[i];
        float4 vb0 = b[i];
        float4 va1 = a[i2];
        float4 vb1 = b[i2];

        // channel of each float4: each (b,c) plane is 65536 float4
        int p0 = i >> 16;  int c0 = p0 - (p0 / 3) * 3;
        int p1 = i2 >> 16; int c1 = p1 - (p1 / 3) * 3;
        unsigned int A0 = (unsigned int)(c0 * NBINS) * REP + copy;
        unsigned int B0 = A0 + (unsigned int)(NCH * NBINS) * REP;
        unsigned int A1 = (unsigned int)(c1 * NBINS) * REP + copy;
        unsigned int B1 = A1 + (unsigned int)(NCH * NBINS) * REP;

        // bin = clip(v,0,255) then truncate (values >= 0)
        #define BIN(v) ((unsigned int)((int)(v) < 0 ? 0 : ((int)(v) > 255 ? 255 : (int)(v))) << 4)
        atomicAdd(&sh[A0 + BIN(va0.x)], 1u);
        atomicAdd(&sh[A0 + BIN(va0.y)], 1u);
        atomicAdd(&sh[A0 + BIN(va0.z)], 1u);
        atomicAdd(&sh[A0 + BIN(va0.w)], 1u);
        atomicAdd(&sh[B0 + BIN(vb0.x)], 1u);
        atomicAdd(&sh[B0 + BIN(vb0.y)], 1u);
        atomicAdd(&sh[B0 + BIN(vb0.z)], 1u);
        atomicAdd(&sh[B0 + BIN(vb0.w)], 1u);
        atomicAdd(&sh[A1 + BIN(va1.x)], 1u);
        atomicAdd(&sh[A1 + BIN(va1.y)], 1u);
        atomicAdd(&sh[A1 + BIN(va1.z)], 1u);
        atomicAdd(&sh[A1 + BIN(va1.w)], 1u);
        atomicAdd(&sh[B1 + BIN(vb1.x)], 1u);
        atomicAdd(&sh[B1 + BIN(vb1.y)], 1u);
        atomicAdd(&sh[B1 + BIN(vb1.z)], 1u);
        atomicAdd(&sh[B1 + BIN(vb1.w)], 1u);
    }
    if (i < n4) {
        float4 va0 = a[i];
        float4 vb0 = b[i];
        int p0 = i >> 16;  int c0 = p0 - (p0 / 3) * 3;
        unsigned int A0 = (unsigned int)(c0 * NBINS) * REP + copy;
        unsigned int B0 = A0 + (unsigned int)(NCH * NBINS) * REP;
        atomicAdd(&sh[A0 + BIN(va0.x)], 1u);
        atomicAdd(&sh[A0 + BIN(va0.y)], 1u);
        atomicAdd(&sh[A0 + BIN(va0.z)], 1u);
        atomicAdd(&sh[A0 + BIN(va0.w)], 1u);
        atomicAdd(&sh[B0 + BIN(vb0.x)], 1u);
        atomicAdd(&sh[B0 + BIN(vb0.y)], 1u);
        atomicAdd(&sh[B0 + BIN(vb0.z)], 1u);
        atomicAdd(&sh[B0 + BIN(vb0.w)], 1u);
    }
    #undef BIN
    __syncthreads();

    // Flush block-private histogram (sum of REP copies) to global.
    for (int k = tid; k < NHIST; k += THREADS) {
        unsigned int v = 0;
        #pragma unroll
        for (int r = 0; r < REP; r++) v += sh[k * REP + r];
        if (v) atomicAdd(&g_hist[k], v);
    }

    // Last-block detection (threadFenceReduction pattern).
    __shared__ unsigned int s_last;
    __threadfence();
    if (tid == 0) {
        unsigned int prev = atomicAdd(&g_count, 1u);
        s_last = (prev == (unsigned int)gridDim.x - 1u) ? 1u : 0u;
    }
    __syncthreads();
    if (!s_last) return;
    __threadfence();

    // ---- Final Bhattacharyya reduce: warp 0, bit-exact R5 code path ----
    if (tid < 32) {
        const int lane = tid;
        float total = 0.0f;
        #pragma unroll 1
        for (int c = 0; c < NCH; c++) {
            const unsigned int* h1 = &g_hist[c * NBINS];
            const unsigned int* h2 = &g_hist[NCH * NBINS + c * NBINS];

            // strided vec2 accumulation: a_v += e[64*j + 2*lane + v]
            float a0 = 0.0f, a1 = 0.0f;
            unsigned int isum1 = 0u, isum2 = 0u;
            #pragma unroll
            for (int j = 0; j < 4; j++) {
                int base = j * 64 + lane * 2;
                unsigned int u10 = __ldcg(&h1[base]);
                unsigned int u11 = __ldcg(&h1[base + 1]);
                unsigned int u20 = __ldcg(&h2[base]);
                unsigned int u21 = __ldcg(&h2[base + 1]);
                float t0 = __fsqrt_rn(__fmul_rn((float)u10, (float)u20));
                float t1 = __fsqrt_rn(__fmul_rn((float)u11, (float)u21));
                a0 = __fadd_rn(a0, t0);
                a1 = __fadd_rn(a1, t1);
                isum1 += u10 + u11;
                isum2 += u20 + u21;
            }

            // independent full shfl-down trees per vector-lane accumulator
            #pragma unroll
            for (int d = 16; d >= 1; d >>= 1) {
                a0 = __fadd_rn(a0, __shfl_down_sync(0xffffffffu, a0, d));
                a1 = __fadd_rn(a1, __shfl_down_sync(0xffffffffu, a1, d));
            }
            float s = __fadd_rn(__shfl_sync(0xffffffffu, a0, 0),
                                __shfl_sync(0xffffffffu, a1, 0));

            #pragma unroll
            for (int d = 16; d >= 1; d >>= 1) {
                isum1 += __shfl_down_sync(0xffffffffu, isum1, d);
                isum2 += __shfl_down_sync(0xffffffffu, isum2, d);
            }
            unsigned int n1 = __shfl_sync(0xffffffffu, isum1, 0);
            unsigned int n2 = __shfl_sync(0xffffffffu, isum2, 0);

            float m1 = __fdiv_rn((float)n1, 256.0f);
            float m2 = __fdiv_rn((float)n2, 256.0f);
            float denom = __fmul_rn(__fsqrt_rn(__fmul_rn(m1, m2)), 256.0f);

            float r = __fdiv_rn(s, denom);
            float t = __fadd_rn(1.0f, -r);   // Sterbenz-exact for r near 1
            if (t < 0.0f) t = 0.0f;
            total = __fadd_rn(total, __fsqrt_rn(t));
        }
        if (lane == 0) out[0] = total;
    }
    __syncthreads();

    // Restore global state to zeros for the next (graph-replayed) call.
    for (int k = tid; k < NHIST; k += THREADS) g_hist[k] = 0u;
    if (tid == 0) g_count = 0u;
}

extern "C" void kernel_launch(void* const* d_in, const int* in_sizes, int n_in,
                              void* d_out, int out_size) {
    const float4* a = (const float4*)d_in[0];
    const float4* b = (const float4*)d_in[1];
    float* out = (float*)d_out;

    int n4 = in_sizes[0] >> 2;   // 6291456 float4 per tensor

    cudaFuncSetAttribute(his_fused_kernel,
                         cudaFuncAttributeMaxDynamicSharedMemorySize, SMEM_BYTES);
    his_fused_kernel<<<BLOCKS, THREADS, SMEM_BYTES>>>(a, b, n4, out);
}

// round 11
// speedup vs baseline: 1.2085x; 1.0484x over previous
#include <cuda_runtime.h>
#include <cuda_bf16.h>

// his_19834158972940: input/label [32,3,512,512] f32 in [0,256).
// Per-channel 256-bin histograms + Bhattacharyya distance, summed -> f32.
//
// Numerics (verified R5/R7/R8, rel_err 0.0): t = 1 - s/denom ~ 7.6e-6 is a
// catastrophic cancellation; passing requires BIT-EXACT replication of the
// reference's float32 reduction order for s = sum(sqrt(h1*h2)):
// legacy XLA:GPU row-reduce — 32 threads, vector_size=2, strided loads
// e[64j+2t+v], independent shfl-down trees (16,8,4,2,1) per vector lane,
// combined AFTER the trees. denom exact (2^23). Preserved verbatim.
//
// Perf (R10 = R9 resubmit; R9 hit an infra container failure, not a kernel
// result): R8 ncu (DRAM 60%, L1 48%, issue 45%) showed the smem-atomic
// pipe still throttling the LDG stream. REP=16 cannot be conflict-free
// (16 words/bin span only 16 banks). This round: LANE-PRIVATE words,
//   counter(region,bin,lane) = sh[(region+bin)*32 + lane]
// bank == lane for every access -> zero bank conflicts, zero intra-warp
// same-address collisions, on every ATOMS. 192KB smem -> 1 block of 1024
// threads per SM (occ 50%); 32 warps x 4 batched LDG.128 is ample MLP to
// saturate HBM. Flush uses rotated uint4 reads to stay conflict-free.

#define NBINS 256
#define NCH 3
#define NHIST (2 * NCH * NBINS)   // 1536 (region+bin) slots
#define THREADS 1024
#define BLOCKS 148                // 1 block/SM, single wave
#define SMEM_WORDS (NHIST * 32)   // 49152
#define SMEM_BYTES (SMEM_WORDS * 4)  // 196608

__device__ unsigned int g_hist[NHIST];   // zero-initialized at module load
__device__ unsigned int g_count;         // arrival counter, reset each call

__global__ void __launch_bounds__(THREADS) his_fused_kernel(
    const float4* __restrict__ a,   // input
    const float4* __restrict__ b,   // label
    int n4,
    float* __restrict__ out)
{
    extern __shared__ unsigned int sh[];   // SMEM_WORDS
    const int tid = threadIdx.x;
    const unsigned int lane = (unsigned int)(tid & 31);

    {   // zero smem (uint4)
        uint4* sh4 = (uint4*)sh;
        for (int i = tid; i < SMEM_WORDS / 4; i += THREADS)
            sh4[i] = make_uint4(0u, 0u, 0u, 0u);
    }
    __syncthreads();

    const int stride = gridDim.x * blockDim.x;

    int i = blockIdx.x * blockDim.x + tid;
    for (; i + stride < n4; i += 2 * stride) {
        int i2 = i + stride;
        // batch loads first (MLP)
        float4 va0 = a[i];
        float4 vb0 = b[i];
        float4 va1 = a[i2];
        float4 vb1 = b[i2];

        // channel: each (b,c) plane is 65536 float4
        int p0 = i >> 16;  int c0 = p0 - (p0 / 3) * 3;
        int p1 = i2 >> 16; int c1 = p1 - (p1 / 3) * 3;
        // word base: (c*256 [+768])*32 + lane
        unsigned int A0 = ((unsigned int)c0 << 13) + lane;            // c*256*32
        unsigned int B0 = A0 + (unsigned int)(NCH * NBINS * 32);
        unsigned int A1 = ((unsigned int)c1 << 13) + lane;
        unsigned int B1 = A1 + (unsigned int)(NCH * NBINS * 32);

        // bin = clip(v,0,255) floor; v >= 0 always, so unsigned min suffices
        #define BIN(v) (umin((unsigned int)(int)(v), 255u) << 5)
        atomicAdd(&sh[A0 + BIN(va0.x)], 1u);
        atomicAdd(&sh[A0 + BIN(va0.y)], 1u);
        atomicAdd(&sh[A0 + BIN(va0.z)], 1u);
        atomicAdd(&sh[A0 + BIN(va0.w)], 1u);
        atomicAdd(&sh[B0 + BIN(vb0.x)], 1u);
        atomicAdd(&sh[B0 + BIN(vb0.y)], 1u);
        atomicAdd(&sh[B0 + BIN(vb0.z)], 1u);
        atomicAdd(&sh[B0 + BIN(vb0.w)], 1u);
        atomicAdd(&sh[A1 + BIN(va1.x)], 1u);
        atomicAdd(&sh[A1 + BIN(va1.y)], 1u);
        atomicAdd(&sh[A1 + BIN(va1.z)], 1u);
        atomicAdd(&sh[A1 + BIN(va1.w)], 1u);
        atomicAdd(&sh[B1 + BIN(vb1.x)], 1u);
        atomicAdd(&sh[B1 + BIN(vb1.y)], 1u);
        atomicAdd(&sh[B1 + BIN(vb1.z)], 1u);
        atomicAdd(&sh[B1 + BIN(vb1.w)], 1u);
    }
    if (i < n4) {
        float4 va0 = a[i];
        float4 vb0 = b[i];
        int p0 = i >> 16;  int c0 = p0 - (p0 / 3) * 3;
        unsigned int A0 = ((unsigned int)c0 << 13) + lane;
        unsigned int B0 = A0 + (unsigned int)(NCH * NBINS * 32);
        atomicAdd(&sh[A0 + BIN(va0.x)], 1u);
        atomicAdd(&sh[A0 + BIN(va0.y)], 1u);
        atomicAdd(&sh[A0 + BIN(va0.z)], 1u);
        atomicAdd(&sh[A0 + BIN(va0.w)], 1u);
        atomicAdd(&sh[B0 + BIN(vb0.x)], 1u);
        atomicAdd(&sh[B0 + BIN(vb0.y)], 1u);
        atomicAdd(&sh[B0 + BIN(vb0.z)], 1u);
        atomicAdd(&sh[B0 + BIN(vb0.w)], 1u);
    }
    #undef BIN
    __syncthreads();

    // Flush: per (region+bin) slot, sum its 32 lane words, add to global.
    // Rotated uint4 reads: thread handling slot k reads group (g+lane)&7,
    // so the 32 lanes of a warp spread across the bank groups each round.
    for (int k = tid; k < NHIST; k += THREADS) {
        const uint4* row = (const uint4*)&sh[k << 5];   // 8 uint4
        unsigned int v = 0;
        #pragma unroll
        for (int g = 0; g < 8; g++) {
            uint4 u = row[(g + lane) & 7];
            v += u.x + u.y + u.z + u.w;
        }
        if (v) atomicAdd(&g_hist[k], v);
    }

    // Last-block detection (threadFenceReduction pattern).
    __shared__ unsigned int s_last;
    __threadfence();
    if (tid == 0) {
        unsigned int prev = atomicAdd(&g_count, 1u);
        s_last = (prev == (unsigned int)gridDim.x - 1u) ? 1u : 0u;
    }
    __syncthreads();
    if (!s_last) return;
    __threadfence();

    // ---- Final Bhattacharyya reduce: warp 0, bit-exact R5 code path ----
    if (tid < 32) {
        const int fl = tid;
        float total = 0.0f;
        #pragma unroll 1
        for (int c = 0; c < NCH; c++) {
            const unsigned int* h1 = &g_hist[c * NBINS];
            const unsigned int* h2 = &g_hist[NCH * NBINS + c * NBINS];

            // strided vec2 accumulation: a_v += e[64*j + 2*lane + v]
            float a0 = 0.0f, a1 = 0.0f;
            unsigned int isum1 = 0u, isum2 = 0u;
            #pragma unroll
            for (int j = 0; j < 4; j++) {
                int base = j * 64 + fl * 2;
                unsigned int u10 = __ldcg(&h1[base]);
                unsigned int u11 = __ldcg(&h1[base + 1]);
                unsigned int u20 = __ldcg(&h2[base]);
                unsigned int u21 = __ldcg(&h2[base + 1]);
                float t0 = __fsqrt_rn(__fmul_rn((float)u10, (float)u20));
                float t1 = __fsqrt_rn(__fmul_rn((float)u11, (float)u21));
                a0 = __fadd_rn(a0, t0);
                a1 = __fadd_rn(a1, t1);
                isum1 += u10 + u11;
                isum2 += u20 + u21;
            }

            // independent full shfl-down trees per vector-lane accumulator
            #pragma unroll
            for (int d = 16; d >= 1; d >>= 1) {
                a0 = __fadd_rn(a0, __shfl_down_sync(0xffffffffu, a0, d));
                a1 = __fadd_rn(a1, __shfl_down_sync(0xffffffffu, a1, d));
            }
            float s = __fadd_rn(__shfl_sync(0xffffffffu, a0, 0),
                                __shfl_sync(0xffffffffu, a1, 0));

            #pragma unroll
            for (int d = 16; d >= 1; d >>= 1) {
                isum1 += __shfl_down_sync(0xffffffffu, isum1, d);
                isum2 += __shfl_down_sync(0xffffffffu, isum2, d);
            }
            unsigned int n1 = __shfl_sync(0xffffffffu, isum1, 0);
            unsigned int n2 = __shfl_sync(0xffffffffu, isum2, 0);

            float m1 = __fdiv_rn((float)n1, 256.0f);
            float m2 = __fdiv_rn((float)n2, 256.0f);
            float denom = __fmul_rn(__fsqrt_rn(__fmul_rn(m1, m2)), 256.0f);

            float r = __fdiv_rn(s, denom);
            float t = __fadd_rn(1.0f, -r);   // Sterbenz-exact for r near 1
            if (t < 0.0f) t = 0.0f;
            total = __fadd_rn(total, __fsqrt_rn(t));
        }
        if (fl == 0) out[0] = total;
    }
    __syncthreads();

    // Restore global state to zeros for the next (graph-replayed) call.
    for (int k = tid; k < NHIST; k += THREADS) g_hist[k] = 0u;
    if (tid == 0) g_count = 0u;
}

extern "C" void kernel_launch(void* const* d_in, const int* in_sizes, int n_in,
                              void* d_out, int out_size) {
    const float4* a = (const float4*)d_in[0];
    const float4* b = (const float4*)d_in[1];
    float* out = (float*)d_out;

    int n4 = in_sizes[0] >> 2;   // 6291456 float4 per tensor

    cudaFuncSetAttribute(his_fused_kernel,
                         cudaFuncAttributeMaxDynamicSharedMemorySize, SMEM_BYTES);
    his_fused_kernel<<<BLOCKS, THREADS, SMEM_BYTES>>>(a, b, n4, out);
}

// round 12
// speedup vs baseline: 1.2094x; 1.0007x over previous
#include <cuda_runtime.h>
#include <cuda_bf16.h>

// his_19834158972940: input/label [32,3,512,512] f32 in [0,256).
// Per-channel 256-bin histograms + Bhattacharyya distance, summed -> f32.
//
// Numerics (verified rel_err 0.0 since R5): t = 1 - s/denom ~ 7.6e-6 is a
// catastrophic cancellation; passing requires BIT-EXACT replication of the
// reference's float32 reduction order for s = sum(sqrt(h1*h2)):
// legacy XLA:GPU row-reduce — 32 threads, vector_size=2, strided loads
// e[64j+2t+v], independent shfl-down trees (16,8,4,2,1) per vector lane,
// combined AFTER the trees. denom exact (2^23). Preserved verbatim.
//
// Perf history: R8 REP16 43.4us (atomics throttle loads) -> R10 lane-private
// conflict-free atomics 41.5us (L1 48->32%, DRAM 62%, issue 36%, occ 49%):
// now memory-LATENCY-bound at occ 50%.
// R11: 4x unroll — all 8 LDG.128 issued before any use (128KB in flight/SM
// vs ~17KB needed), __ldcs streaming loads. Lane-private smem histogram
// unchanged: counter(slot,lane) = sh[slot*32+lane], bank==lane -> zero
// conflicts. 192KB smem, 1 block/SM.

#define NBINS 256
#define NCH 3
#define NHIST (2 * NCH * NBINS)   // 1536 (region+bin) slots
#define THREADS 1024
#define BLOCKS 148                // 1 block/SM, single wave
#define SMEM_WORDS (NHIST * 32)   // 49152
#define SMEM_BYTES (SMEM_WORDS * 4)  // 196608

__device__ unsigned int g_hist[NHIST];   // zero-initialized at module load
__device__ unsigned int g_count;         // arrival counter, reset each call

__global__ void __launch_bounds__(THREADS, 1) his_fused_kernel(
    const float4* __restrict__ a,   // input
    const float4* __restrict__ b,   // label
    int n4,
    float* __restrict__ out)
{
    extern __shared__ unsigned int sh[];   // SMEM_WORDS
    const int tid = threadIdx.x;
    const unsigned int lane = (unsigned int)(tid & 31);

    {   // zero smem (uint4)
        uint4* sh4 = (uint4*)sh;
        for (int i = tid; i < SMEM_WORDS / 4; i += THREADS)
            sh4[i] = make_uint4(0u, 0u, 0u, 0u);
    }
    __syncthreads();

    const int s = gridDim.x * blockDim.x;

    // bin = clip(v,0,255) floor; v >= 0 always, so unsigned min suffices.
    #define BIN(v) (umin((unsigned int)(int)(v), 255u) << 5)
    // channel of float4 index: each (b,c) plane is 65536 float4
    #define CBASE(idx) ((((unsigned int)((idx) >> 16) % 3u) << 13) + lane)

    int i = blockIdx.x * blockDim.x + tid;
    for (; i + 3 * s < n4; i += 4 * s) {
        // issue ALL 8 loads before any use (MLP), streaming hint
        float4 va0 = __ldcs(&a[i]);
        float4 va1 = __ldcs(&a[i + s]);
        float4 va2 = __ldcs(&a[i + 2 * s]);
        float4 va3 = __ldcs(&a[i + 3 * s]);
        float4 vb0 = __ldcs(&b[i]);
        float4 vb1 = __ldcs(&b[i + s]);
        float4 vb2 = __ldcs(&b[i + 2 * s]);
        float4 vb3 = __ldcs(&b[i + 3 * s]);

        unsigned int A0 = CBASE(i);
        unsigned int A1 = CBASE(i + s);
        unsigned int A2 = CBASE(i + 2 * s);
        unsigned int A3 = CBASE(i + 3 * s);
        const unsigned int RB = (unsigned int)(NCH * NBINS * 32);

        atomicAdd(&sh[A0 + BIN(va0.x)], 1u);
        atomicAdd(&sh[A0 + BIN(va0.y)], 1u);
        atomicAdd(&sh[A0 + BIN(va0.z)], 1u);
        atomicAdd(&sh[A0 + BIN(va0.w)], 1u);
        atomicAdd(&sh[A1 + BIN(va1.x)], 1u);
        atomicAdd(&sh[A1 + BIN(va1.y)], 1u);
        atomicAdd(&sh[A1 + BIN(va1.z)], 1u);
        atomicAdd(&sh[A1 + BIN(va1.w)], 1u);
        atomicAdd(&sh[A2 + BIN(va2.x)], 1u);
        atomicAdd(&sh[A2 + BIN(va2.y)], 1u);
        atomicAdd(&sh[A2 + BIN(va2.z)], 1u);
        atomicAdd(&sh[A2 + BIN(va2.w)], 1u);
        atomicAdd(&sh[A3 + BIN(va3.x)], 1u);
        atomicAdd(&sh[A3 + BIN(va3.y)], 1u);
        atomicAdd(&sh[A3 + BIN(va3.z)], 1u);
        atomicAdd(&sh[A3 + BIN(va3.w)], 1u);
        atomicAdd(&sh[A0 + RB + BIN(vb0.x)], 1u);
        atomicAdd(&sh[A0 + RB + BIN(vb0.y)], 1u);
        atomicAdd(&sh[A0 + RB + BIN(vb0.z)], 1u);
        atomicAdd(&sh[A0 + RB + BIN(vb0.w)], 1u);
        atomicAdd(&sh[A1 + RB + BIN(vb1.x)], 1u);
        atomicAdd(&sh[A1 + RB + BIN(vb1.y)], 1u);
        atomicAdd(&sh[A1 + RB + BIN(vb1.z)], 1u);
        atomicAdd(&sh[A1 + RB + BIN(vb1.w)], 1u);
        atomicAdd(&sh[A2 + RB + BIN(vb2.x)], 1u);
        atomicAdd(&sh[A2 + RB + BIN(vb2.y)], 1u);
        atomicAdd(&sh[A2 + RB + BIN(vb2.z)], 1u);
        atomicAdd(&sh[A2 + RB + BIN(vb2.w)], 1u);
        atomicAdd(&sh[A3 + RB + BIN(vb3.x)], 1u);
        atomicAdd(&sh[A3 + RB + BIN(vb3.y)], 1u);
        atomicAdd(&sh[A3 + RB + BIN(vb3.z)], 1u);
        atomicAdd(&sh[A3 + RB + BIN(vb3.w)], 1u);
    }
    for (; i < n4; i += s) {
        float4 va0 = __ldcs(&a[i]);
        float4 vb0 = __ldcs(&b[i]);
        unsigned int A0 = CBASE(i);
        unsigned int B0 = A0 + (unsigned int)(NCH * NBINS * 32);
        atomicAdd(&sh[A0 + BIN(va0.x)], 1u);
        atomicAdd(&sh[A0 + BIN(va0.y)], 1u);
        atomicAdd(&sh[A0 + BIN(va0.z)], 1u);
        atomicAdd(&sh[A0 + BIN(va0.w)], 1u);
        atomicAdd(&sh[B0 + BIN(vb0.x)], 1u);
        atomicAdd(&sh[B0 + BIN(vb0.y)], 1u);
        atomicAdd(&sh[B0 + BIN(vb0.z)], 1u);
        atomicAdd(&sh[B0 + BIN(vb0.w)], 1u);
    }
    #undef BIN
    #undef CBASE
    __syncthreads();

    // Flush: per (region+bin) slot, sum its 32 lane words, add to global.
    // Rotated uint4 reads spread a warp's lanes across the bank groups.
    for (int k = tid; k < NHIST; k += THREADS) {
        const uint4* row = (const uint4*)&sh[k << 5];   // 8 uint4
        unsigned int v = 0;
        #pragma unroll
        for (int g = 0; g < 8; g++) {
            uint4 u = row[(g + lane) & 7];
            v += u.x + u.y + u.z + u.w;
        }
        if (v) atomicAdd(&g_hist[k], v);
    }

    // Last-block detection (threadFenceReduction pattern).
    __shared__ unsigned int s_last;
    __threadfence();
    if (tid == 0) {
        unsigned int prev = atomicAdd(&g_count, 1u);
        s_last = (prev == (unsigned int)gridDim.x - 1u) ? 1u : 0u;
    }
    __syncthreads();
    if (!s_last) return;
    __threadfence();

    // ---- Final Bhattacharyya reduce: warp 0, bit-exact R5 code path ----
    if (tid < 32) {
        const int fl = tid;
        float total = 0.0f;
        #pragma unroll 1
        for (int c = 0; c < NCH; c++) {
            const unsigned int* h1 = &g_hist[c * NBINS];
            const unsigned int* h2 = &g_hist[NCH * NBINS + c * NBINS];

            // strided vec2 accumulation: a_v += e[64*j + 2*lane + v]
            float a0 = 0.0f, a1 = 0.0f;
            unsigned int isum1 = 0u, isum2 = 0u;
            #pragma unroll
            for (int j = 0; j < 4; j++) {
                int base = j * 64 + fl * 2;
                unsigned int u10 = __ldcg(&h1[base]);
                unsigned int u11 = __ldcg(&h1[base + 1]);
                unsigned int u20 = __ldcg(&h2[base]);
                unsigned int u21 = __ldcg(&h2[base + 1]);
                float t0 = __fsqrt_rn(__fmul_rn((float)u10, (float)u20));
                float t1 = __fsqrt_rn(__fmul_rn((float)u11, (float)u21));
                a0 = __fadd_rn(a0, t0);
                a1 = __fadd_rn(a1, t1);
                isum1 += u10 + u11;
                isum2 += u20 + u21;
            }

            // independent full shfl-down trees per vector-lane accumulator
            #pragma unroll
            for (int d = 16; d >= 1; d >>= 1) {
                a0 = __fadd_rn(a0, __shfl_down_sync(0xffffffffu, a0, d));
                a1 = __fadd_rn(a1, __shfl_down_sync(0xffffffffu, a1, d));
            }
            float s2 = __fadd_rn(__shfl_sync(0xffffffffu, a0, 0),
                                 __shfl_sync(0xffffffffu, a1, 0));

            #pragma unroll
            for (int d = 16; d >= 1; d >>= 1) {
                isum1 += __shfl_down_sync(0xffffffffu, isum1, d);
                isum2 += __shfl_down_sync(0xffffffffu, isum2, d);
            }
            unsigned int n1 = __shfl_sync(0xffffffffu, isum1, 0);
            unsigned int n2 = __shfl_sync(0xffffffffu, isum2, 0);

            float m1 = __fdiv_rn((float)n1, 256.0f);
            float m2 = __fdiv_rn((float)n2, 256.0f);
            float denom = __fmul_rn(__fsqrt_rn(__fmul_rn(m1, m2)), 256.0f);

            float r = __fdiv_rn(s2, denom);
            float t = __fadd_rn(1.0f, -r);   // Sterbenz-exact for r near 1
            if (t < 0.0f) t = 0.0f;
            total = __fadd_rn(total, __fsqrt_rn(t));
        }
        if (fl == 0) out[0] = total;
    }
    __syncthreads();

    // Restore global state to zeros for the next (graph-replayed) call.
    for (int k = tid; k < NHIST; k += THREADS) g_hist[k] = 0u;
    if (tid == 0) g_count = 0u;
}

extern "C" void kernel_launch(void* const* d_in, const int* in_sizes, int n_in,
                              void* d_out, int out_size) {
    const float4* a = (const float4*)d_in[0];
    const float4* b = (const float4*)d_in[1];
    float* out = (float*)d_out;

    int n4 = in_sizes[0] >> 2;   // 6291456 float4 per tensor

    cudaFuncSetAttribute(his_fused_kernel,
                         cudaFuncAttributeMaxDynamicSharedMemorySize, SMEM_BYTES);
    his_fused_kernel<<<BLOCKS, THREADS, SMEM_BYTES>>>(a, b, n4, out);
}